// round 5
// baseline (speedup 1.0000x reference)
#include <cuda_runtime.h>

// ---------------------------------------------------------------------------
// SegFormerXAttention: B=4, Lv=1024, Lt=256, H=16, DH=64, D=1024
//
// Pipeline:
//   0) detect_mask_mode : figure out the on-device dtype of the bool masks
//   1) proj_gemm x2     : per-token projections (6 slots each) for vid & txt
//   2) logits_kernel    : batched (b,h) GEMM Q·K^T (K=64) + mask fill (-1e4)
//   3) softmax_kernel   : row softmax over 1280 keys, fused * 1/sqrt(64)
//   4) pv_kernel        : batched (b,h) GEMM P·V (K=1280) -> output layout
// ---------------------------------------------------------------------------

namespace cfg {
constexpr int D  = 1024;
constexpr int H  = 16;
constexpr int DH = 64;
constexpr int B  = 4;
constexpr int LV = 1024;
constexpr int LT = 256;
constexpr int LK = LV + LT;   // 1280
constexpr int PW = 6 * D;     // 6144 columns in projection scratch
}

// slot layout per token (x1024 cols each):
//  projV: 0=Q v-stream seg-vid (Wq_v2v) 1=Q v-stream seg-txt (Wq_t2v)
//         2=K v-stream (Wk_v2v)         3=K t-stream (Wk_v2t)
//         4=V v-stream (Wv_v2v)         5=V t-stream (Wv_v2t)
//  projT: 0=Q t-stream seg-vid (Wq_v2t) 1=Q t-stream seg-txt (Wq_t2t)
//         2=K v-stream (Wk_t2v)         3=K t-stream (Wk_t2t)
//         4=V v-stream (Wv_t2v)         5=V t-stream (Wv_t2t)

__device__ float g_projV[(size_t)cfg::B * cfg::LV * cfg::PW];              //  96 MB
__device__ float g_projT[(size_t)cfg::B * cfg::LT * cfg::PW];              //  24 MB
__device__ float g_Sv[(size_t)cfg::B * cfg::H * cfg::LV * cfg::LK];        // 335 MB
__device__ float g_St[(size_t)cfg::B * cfg::H * cfg::LT * cfg::LK];        //  84 MB

// 0 = float32 (1.0f/0.0f), 1 = int32 (1/0), 2 = packed uint8 bool
__device__ int g_maskMode;

__global__ void detect_mask_mode(const unsigned int* m) {
    if (threadIdx.x != 0) return;
    bool isF = false, isB = false;
    for (int i = 0; i < 64; i++) {
        unsigned int w = m[i];
        if (w == 0x3F800000u) isF = true;   // float 1.0f — impossible from 0/1 bytes
        if (w == 0x01010101u) isB = true;   // four adjacent true bytes
    }
    g_maskMode = isF ? 0 : (isB ? 2 : 1);
}

__device__ __forceinline__ bool mask_at(const void* m, int i) {
    const int mode = g_maskMode;
    if (mode == 0) return ((const float*)m)[i] != 0.0f;
    if (mode == 1) return ((const int*)m)[i] != 0;
    return ((const unsigned char*)m)[i] != 0;
}

struct ProjArgs {
    const float* A;          // [M, D]
    const float* W[6];       // each [D, D] row-major (out, in)
    const float* bias[6];    // each [D]
    int M;
    int isVid;               // 1 -> write g_projV, 0 -> g_projT
};

// ---------------------------------------------------------------------------
// 128x128 block-tile SGEMM, K-step 8, 256 threads, 8x8 micro-tile.
// C[m, n] = sum_k A[m,k] * W[sel][col,k] + bias[sel][col]
//   where sel = n/1024, col = n%1024 (torch Linear: y = x @ W^T + b)
// ---------------------------------------------------------------------------
__global__ __launch_bounds__(256) void proj_gemm(ProjArgs args) {
    using namespace cfg;
    float* C = args.isVid ? g_projV : g_projT;

    const int t  = threadIdx.x;
    const int m0 = blockIdx.y * 128;
    const int n0 = blockIdx.x * 128;
    const int sel = n0 >> 10;
    const int c0  = n0 & (D - 1);
    const float* W = args.W[sel];

    __shared__ float As[8][128];
    __shared__ float Bs[8][128];

    const int lr = t >> 1;           // 0..127
    const int lk = (t & 1) << 2;     // 0 or 4

    const float* Aptr = args.A + (size_t)(m0 + lr) * D + lk;
    const float* Wptr = W      + (size_t)(c0 + lr) * D + lk;

    float acc[8][8];
#pragma unroll
    for (int i = 0; i < 8; i++)
#pragma unroll
        for (int j = 0; j < 8; j++) acc[i][j] = 0.0f;

    const int ty = t >> 4;   // 0..15  (row group)
    const int tx = t & 15;   // 0..15  (col group)

    for (int k0 = 0; k0 < D; k0 += 8) {
        float4 av = *(const float4*)(Aptr + k0);
        float4 wv = *(const float4*)(Wptr + k0);
        __syncthreads();
        As[lk + 0][lr] = av.x; As[lk + 1][lr] = av.y;
        As[lk + 2][lr] = av.z; As[lk + 3][lr] = av.w;
        Bs[lk + 0][lr] = wv.x; Bs[lk + 1][lr] = wv.y;
        Bs[lk + 2][lr] = wv.z; Bs[lk + 3][lr] = wv.w;
        __syncthreads();
#pragma unroll
        for (int kk = 0; kk < 8; kk++) {
            float4 a0 = *(const float4*)&As[kk][ty * 8];
            float4 a1 = *(const float4*)&As[kk][ty * 8 + 4];
            float4 b0 = *(const float4*)&Bs[kk][tx * 8];
            float4 b1 = *(const float4*)&Bs[kk][tx * 8 + 4];
            float a[8] = {a0.x, a0.y, a0.z, a0.w, a1.x, a1.y, a1.z, a1.w};
            float b[8] = {b0.x, b0.y, b0.z, b0.w, b1.x, b1.y, b1.z, b1.w};
#pragma unroll
            for (int i = 0; i < 8; i++)
#pragma unroll
                for (int j = 0; j < 8; j++)
                    acc[i][j] += a[i] * b[j];
        }
    }

    const float* bias = args.bias[sel];
#pragma unroll
    for (int i = 0; i < 8; i++) {
        const int m = m0 + ty * 8 + i;
        float* crow = C + (size_t)m * PW + n0 + tx * 8;
#pragma unroll
        for (int j = 0; j < 8; j++)
            crow[j] = acc[i][j] + bias[c0 + tx * 8 + j];
    }
}

// ---------------------------------------------------------------------------
// Logits: S[b,h,q,k] = Q(b,q,h,:)·K(b,k,h,:), masked fill -1e4.
// Batched over (b,h). 64x64 output tile per block, K(=dh)=64 in one shot.
// The Q slot depends on the key segment (different Wq for vid vs txt keys).
// ---------------------------------------------------------------------------
__global__ __launch_bounds__(256) void logits_kernel(
    int isV, const void* vmask, const void* tmask)
{
    using namespace cfg;
    const int Lq = isV ? LV : LT;
    const int kslot = isV ? 2 : 3;
    float* S = isV ? g_Sv : g_St;
    const float* projQ = isV ? g_projV : g_projT;
    const void* qmask = isV ? vmask : tmask;

    const int bh = blockIdx.z;
    const int b  = bh >> 4;
    const int h  = bh & 15;
    const int q0 = blockIdx.y * 64;
    const int k0 = blockIdx.x * 64;
    const int t  = threadIdx.x;

    const bool segTxt = (k0 >= LV);
    const int qslot = segTxt ? 1 : 0;

    __shared__ float Qs[64][65];   // [d][q], pad to dodge conflicts
    __shared__ float Ks[64][65];   // [d][k]

    {
        const int r  = t >> 4;            // 0..15
        const int dc = (t & 15) * 4;      // 0..60
        const float* qp = projQ + ((size_t)(b * Lq + q0 + r)) * PW
                        + qslot * D + h * DH + dc;
        const float* kp;
        if (!segTxt)
            kp = g_projV + ((size_t)(b * LV + k0 + r)) * PW + kslot * D + h * DH + dc;
        else
            kp = g_projT + ((size_t)(b * LT + (k0 - LV) + r)) * PW + kslot * D + h * DH + dc;
#pragma unroll
        for (int it = 0; it < 4; it++) {
            const int row = r + it * 16;
            float4 qv = *(const float4*)(qp + (size_t)(it * 16) * PW);
            Qs[dc + 0][row] = qv.x; Qs[dc + 1][row] = qv.y;
            Qs[dc + 2][row] = qv.z; Qs[dc + 3][row] = qv.w;
            float4 kv = *(const float4*)(kp + (size_t)(it * 16) * PW);
            Ks[dc + 0][row] = kv.x; Ks[dc + 1][row] = kv.y;
            Ks[dc + 2][row] = kv.z; Ks[dc + 3][row] = kv.w;
        }
    }
    __syncthreads();

    const int ty = t >> 4;          // q group
    const int tx = t & 15;          // k group
    const int qb = ty * 4, kb = tx * 4;

    float acc[4][4] = {};
#pragma unroll 8
    for (int kk = 0; kk < 64; kk++) {
        float a[4], bb[4];
#pragma unroll
        for (int i = 0; i < 4; i++) a[i]  = Qs[kk][qb + i];
#pragma unroll
        for (int j = 0; j < 4; j++) bb[j] = Ks[kk][kb + j];
#pragma unroll
        for (int i = 0; i < 4; i++)
#pragma unroll
            for (int j = 0; j < 4; j++)
                acc[i][j] += a[i] * bb[j];
    }

#pragma unroll
    for (int i = 0; i < 4; i++) {
        const int q = q0 + qb + i;
        const bool mq = mask_at(qmask, b * Lq + q);
        float* srow = S + ((size_t)bh * Lq + q) * LK + k0 + kb;
#pragma unroll
        for (int j = 0; j < 4; j++) {
            const int k = k0 + kb + j;
            const bool mk = segTxt ? mask_at(tmask, b * LT + k - LV)
                                   : mask_at(vmask, b * LV + k);
            srow[j] = (mq && mk) ? acc[i][j] : -10000.0f;
        }
    }
}

// ---------------------------------------------------------------------------
// Row softmax over 1280 keys, fused * 1/sqrt(DH) = 0.125. One block per row.
// ---------------------------------------------------------------------------
__global__ __launch_bounds__(256) void softmax_kernel(int isV) {
    using namespace cfg;
    float* S = isV ? g_Sv : g_St;
    float* p = S + (size_t)blockIdx.x * LK;
    const int t = threadIdx.x;
    const int lane = t & 31, warp = t >> 5;

    float v[5];
    float mx = -1e30f;
#pragma unroll
    for (int i = 0; i < 5; i++) { v[i] = p[t + i * 256]; mx = fmaxf(mx, v[i]); }
#pragma unroll
    for (int o = 16; o; o >>= 1) mx = fmaxf(mx, __shfl_xor_sync(0xffffffffu, mx, o));

    __shared__ float red[8];
    if (lane == 0) red[warp] = mx;
    __syncthreads();
    float m_all = red[0];
#pragma unroll
    for (int i = 1; i < 8; i++) m_all = fmaxf(m_all, red[i]);

    float sum = 0.0f;
#pragma unroll
    for (int i = 0; i < 5; i++) { v[i] = __expf(v[i] - m_all); sum += v[i]; }
#pragma unroll
    for (int o = 16; o; o >>= 1) sum += __shfl_xor_sync(0xffffffffu, sum, o);
    __syncthreads();
    if (lane == 0) red[warp] = sum;
    __syncthreads();
    float s_all = 0.0f;
#pragma unroll
    for (int i = 0; i < 8; i++) s_all += red[i];

    const float sc = 0.125f / s_all;
#pragma unroll
    for (int i = 0; i < 5; i++) p[t + i * 256] = v[i] * sc;
}

// ---------------------------------------------------------------------------
// out[b,q,h,dh] = sum_k P[b,h,q,k] * V[b,k,h,dh]. 64 q x 64 dh per block.
// ---------------------------------------------------------------------------
__global__ __launch_bounds__(256) void pv_kernel(int isV, float* out) {
    using namespace cfg;
    const int Lq = isV ? LV : LT;
    const int vslot = isV ? 4 : 5;
    const float* S = isV ? g_Sv : g_St;

    const int bh = blockIdx.z;
    const int b  = bh >> 4;
    const int h  = bh & 15;
    const int q0 = blockIdx.y * 64;
    const int t  = threadIdx.x;

    __shared__ float Ps[64][65];   // [k][q]
    __shared__ float Vs[64][65];   // [k][d]

    const int ty = t >> 4, tx = t & 15;
    const int qb = ty * 4, db = tx * 4;

    float acc[4][4] = {};

    const int r  = t >> 4;
    const int cc = (t & 15) * 4;

    for (int k0 = 0; k0 < LK; k0 += 64) {
        const bool segTxt = (k0 >= LV);
        __syncthreads();
#pragma unroll
        for (int it = 0; it < 4; it++) {
            const int row = r + it * 16;
            // P tile: rows = q, cols = k; store transposed
            float4 pv = *(const float4*)(S + ((size_t)bh * Lq + q0 + row) * LK + k0 + cc);
            Ps[cc + 0][row] = pv.x; Ps[cc + 1][row] = pv.y;
            Ps[cc + 2][row] = pv.z; Ps[cc + 3][row] = pv.w;
            // V tile: rows = k, cols = d; store natural
            const int kidx = k0 + row;
            const float* vp;
            if (!segTxt)
                vp = g_projV + ((size_t)(b * LV + kidx)) * PW + vslot * D + h * DH + cc;
            else
                vp = g_projT + ((size_t)(b * LT + kidx - LV)) * PW + vslot * D + h * DH + cc;
            float4 vv = *(const float4*)vp;
            Vs[row][cc + 0] = vv.x; Vs[row][cc + 1] = vv.y;
            Vs[row][cc + 2] = vv.z; Vs[row][cc + 3] = vv.w;
        }
        __syncthreads();
#pragma unroll 8
        for (int kk = 0; kk < 64; kk++) {
            float a[4], bb[4];
#pragma unroll
            for (int i = 0; i < 4; i++) a[i]  = Ps[kk][qb + i];
#pragma unroll
            for (int j = 0; j < 4; j++) bb[j] = Vs[kk][db + j];
#pragma unroll
            for (int i = 0; i < 4; i++)
#pragma unroll
                for (int j = 0; j < 4; j++)
                    acc[i][j] += a[i] * bb[j];
        }
    }

#pragma unroll
    for (int i = 0; i < 4; i++) {
        const int q = q0 + qb + i;
        float* orow = out + ((size_t)(b * Lq + q)) * D + h * DH + db;
#pragma unroll
        for (int j = 0; j < 4; j++) orow[j] = acc[i][j];
    }
}

// ---------------------------------------------------------------------------
extern "C" void kernel_launch(void* const* d_in, const int* in_sizes, int n_in,
                              void* d_out, int out_size) {
    using namespace cfg;
    const float* vid_feat = (const float*)d_in[0];
    const void*  vid_mask = d_in[1];
    const float* txt_feat = (const float*)d_in[2];
    const void*  txt_mask = d_in[3];
    const float* W_v2v = (const float*)d_in[4];
    const float* b_v2v = (const float*)d_in[5];
    const float* W_t2v = (const float*)d_in[6];
    const float* b_t2v = (const float*)d_in[7];
    const float* W_v2t = (const float*)d_in[8];
    const float* b_v2t = (const float*)d_in[9];
    const float* W_t2t = (const float*)d_in[10];
    const float* b_t2t = (const float*)d_in[11];
    float* out = (float*)d_out;

    const int DD = D * D;

    detect_mask_mode<<<1, 32>>>((const unsigned int*)vid_mask);

    ProjArgs av;
    av.A = vid_feat; av.M = B * LV; av.isVid = 1;
    av.W[0] = W_v2v;          av.bias[0] = b_v2v;
    av.W[1] = W_t2v;          av.bias[1] = b_t2v;
    av.W[2] = W_v2v + DD;     av.bias[2] = b_v2v + D;
    av.W[3] = W_v2t + DD;     av.bias[3] = b_v2t + D;
    av.W[4] = W_v2v + 2*DD;   av.bias[4] = b_v2v + 2*D;
    av.W[5] = W_v2t + 2*DD;   av.bias[5] = b_v2t + 2*D;

    ProjArgs at;
    at.A = txt_feat; at.M = B * LT; at.isVid = 0;
    at.W[0] = W_v2t;          at.bias[0] = b_v2t;
    at.W[1] = W_t2t;          at.bias[1] = b_t2t;
    at.W[2] = W_t2v + DD;     at.bias[2] = b_t2v + D;
    at.W[3] = W_t2t + DD;     at.bias[3] = b_t2t + D;
    at.W[4] = W_t2v + 2*DD;   at.bias[4] = b_t2v + 2*D;
    at.W[5] = W_t2t + 2*DD;   at.bias[5] = b_t2t + 2*D;

    proj_gemm<<<dim3(PW / 128, (B * LV) / 128, 1), 256>>>(av);
    proj_gemm<<<dim3(PW / 128, (B * LT) / 128, 1), 256>>>(at);

    logits_kernel<<<dim3(LK / 64, LV / 64, B * H), 256>>>(1, vid_mask, txt_mask);
    logits_kernel<<<dim3(LK / 64, LT / 64, B * H), 256>>>(0, vid_mask, txt_mask);

    softmax_kernel<<<B * H * LV, 256>>>(1);
    softmax_kernel<<<B * H * LT, 256>>>(0);

    pv_kernel<<<dim3(1, LV / 64, B * H), 256>>>(1, out);
    pv_kernel<<<dim3(1, LT / 64, B * H), 256>>>(0, out + (size_t)B * LV * D);
}

// round 7
// speedup vs baseline: 1.5211x; 1.5211x over previous
#include <cuda_runtime.h>
#include <cuda_bf16.h>
#include <cstdint>

// ---------------------------------------------------------------------------
// SegFormerXAttention: B=4, Lv=1024, Lt=256, H=16, DH=64, D=1024
//
//   0) detect_mask_mode : on-device dtype of the bool masks
//   1) convert_one x14  : fp32 -> (bf16 hi, bf16 lo) split of A and W slabs
//   2) proj_mma x2      : mma.sync bf16 3-term-split GEMM -> fp32 projections
//                         (tcgen05 is unusable: harness PTX target is
//                          compute_103 without the 'a' feature set)
//   3) logits_kernel    : batched (b,h) GEMM Q.K^T (K=64) + mask fill (-1e4)
//   4) softmax_kernel   : row softmax over 1280 keys, fused * 1/sqrt(64)
//   5) pv_kernel        : batched (b,h) GEMM P.V -> output layout
// ---------------------------------------------------------------------------

namespace cfg {
constexpr int D  = 1024;
constexpr int H  = 16;
constexpr int DH = 64;
constexpr int B  = 4;
constexpr int LV = 1024;
constexpr int LT = 256;
constexpr int LK = LV + LT;   // 1280
constexpr int PW = 6 * D;     // 6144 columns in projection scratch
constexpr int DD = D * D;
}

__device__ float g_projV[(size_t)cfg::B * cfg::LV * cfg::PW];              //  96 MB
__device__ float g_projT[(size_t)cfg::B * cfg::LT * cfg::PW];              //  24 MB
__device__ float g_Sv[(size_t)cfg::B * cfg::H * cfg::LV * cfg::LK];        // 335 MB
__device__ float g_St[(size_t)cfg::B * cfg::H * cfg::LT * cfg::LK];        //  84 MB

// bf16 hi/lo splits
__device__ __nv_bfloat16 g_AVhi[(size_t)cfg::B * cfg::LV * cfg::D];
__device__ __nv_bfloat16 g_AVlo[(size_t)cfg::B * cfg::LV * cfg::D];
__device__ __nv_bfloat16 g_AThi[(size_t)cfg::B * cfg::LT * cfg::D];
__device__ __nv_bfloat16 g_ATlo[(size_t)cfg::B * cfg::LT * cfg::D];
__device__ __nv_bfloat16 g_WVhi[(size_t)6 * cfg::DD];
__device__ __nv_bfloat16 g_WVlo[(size_t)6 * cfg::DD];
__device__ __nv_bfloat16 g_WThi[(size_t)6 * cfg::DD];
__device__ __nv_bfloat16 g_WTlo[(size_t)6 * cfg::DD];

// 0 = float32 (1.0f/0.0f), 1 = int32 (1/0), 2 = packed uint8 bool
__device__ int g_maskMode;

__global__ void detect_mask_mode(const unsigned int* m) {
    if (threadIdx.x != 0) return;
    bool isF = false, isB = false;
    for (int i = 0; i < 64; i++) {
        unsigned int w = m[i];
        if (w == 0x3F800000u) isF = true;
        if (w == 0x01010101u) isB = true;
    }
    g_maskMode = isF ? 0 : (isB ? 2 : 1);
}

__device__ __forceinline__ bool mask_at(const void* m, int i) {
    const int mode = g_maskMode;
    if (mode == 0) return ((const float*)m)[i] != 0.0f;
    if (mode == 1) return ((const int*)m)[i] != 0;
    return ((const unsigned char*)m)[i] != 0;
}

// ---------------------------------------------------------------------------
// fp32 -> bf16 hi/lo split.  dst_id: 0=AV 1=AT 2=WV(+slot) 3=WT(+slot)
// ---------------------------------------------------------------------------
__global__ __launch_bounds__(256) void convert_one(
    const float* __restrict__ src, int dst_id, int slot, int n4)
{
    int i = blockIdx.x * blockDim.x + threadIdx.x;
    if (i >= n4) return;
    __nv_bfloat16 *hi, *lo;
    switch (dst_id) {
        case 0:  hi = g_AVhi;                          lo = g_AVlo;                          break;
        case 1:  hi = g_AThi;                          lo = g_ATlo;                          break;
        case 2:  hi = g_WVhi + (size_t)slot * cfg::DD; lo = g_WVlo + (size_t)slot * cfg::DD; break;
        default: hi = g_WThi + (size_t)slot * cfg::DD; lo = g_WTlo + (size_t)slot * cfg::DD; break;
    }
    float4 v = ((const float4*)src)[i];
    __nv_bfloat16 h0 = __float2bfloat16(v.x);
    __nv_bfloat16 h1 = __float2bfloat16(v.y);
    __nv_bfloat16 h2 = __float2bfloat16(v.z);
    __nv_bfloat16 h3 = __float2bfloat16(v.w);
    __nv_bfloat16 l0 = __float2bfloat16(v.x - __bfloat162float(h0));
    __nv_bfloat16 l1 = __float2bfloat16(v.y - __bfloat162float(h1));
    __nv_bfloat16 l2 = __float2bfloat16(v.z - __bfloat162float(h2));
    __nv_bfloat16 l3 = __float2bfloat16(v.w - __bfloat162float(h3));
    __nv_bfloat162* hp = (__nv_bfloat162*)(hi + (size_t)i * 4);
    __nv_bfloat162* lp = (__nv_bfloat162*)(lo + (size_t)i * 4);
    hp[0] = __nv_bfloat162(h0, h1); hp[1] = __nv_bfloat162(h2, h3);
    lp[0] = __nv_bfloat162(l0, l1); lp[1] = __nv_bfloat162(l2, l3);
}

// ---------------------------------------------------------------------------
// mma.sync / ldmatrix / cp.async helpers (all non-'a' PTX, sm_80+)
// ---------------------------------------------------------------------------
__device__ __forceinline__ uint32_t smem_u32(const void* p) {
    uint32_t a;
    asm("{ .reg .u64 t; cvta.to.shared.u64 t, %1; cvt.u32.u64 %0, t; }" : "=r"(a) : "l"(p));
    return a;
}
__device__ __forceinline__ void mma16816(float* d, const uint32_t* a, const uint32_t* b) {
    asm volatile(
        "mma.sync.aligned.m16n8k16.row.col.f32.bf16.bf16.f32 "
        "{%0,%1,%2,%3}, {%4,%5,%6,%7}, {%8,%9}, {%0,%1,%2,%3};"
        : "+f"(d[0]), "+f"(d[1]), "+f"(d[2]), "+f"(d[3])
        : "r"(a[0]), "r"(a[1]), "r"(a[2]), "r"(a[3]), "r"(b[0]), "r"(b[1]));
}
__device__ __forceinline__ void ldsm_x4(uint32_t* r, uint32_t addr) {
    asm volatile("ldmatrix.sync.aligned.m8n8.x4.shared.b16 {%0,%1,%2,%3}, [%4];"
                 : "=r"(r[0]), "=r"(r[1]), "=r"(r[2]), "=r"(r[3]) : "r"(addr));
}
__device__ __forceinline__ void cp16(uint32_t dst, const void* src) {
    asm volatile("cp.async.cg.shared.global [%0], [%1], 16;" :: "r"(dst), "l"(src));
}
#define CP_COMMIT() asm volatile("cp.async.commit_group;" ::: "memory")
#define CP_WAIT(N)  asm volatile("cp.async.wait_group %0;" :: "n"(N) : "memory")

// ---------------------------------------------------------------------------
// HMMA projection GEMM: C[m, n0+j] = sum_k A[m,k]*W[sel][c0+j,k] + bias
// 128x128 tile / CTA, K=1024 in 16 chunks of 64, 3-term bf16 split.
// 8 warps, each owning 64x32 (4x4 m16n8 atoms). 2-stage cp.async pipeline.
// SMEM per stage: Ahi|Alo|Bhi|Blo, each 128x64 bf16 swizzled (16 KB) = 64 KB.
// ---------------------------------------------------------------------------
struct TCBias { const float* p[6]; };

__global__ __launch_bounds__(256) void proj_mma(int isVid, TCBias bias) {
    using namespace cfg;
    extern __shared__ char sm[];
    uint32_t sbase = smem_u32(sm);
    uint32_t padb  = (1024u - (sbase & 1023u)) & 1023u;
    const uint32_t sa = sbase + padb;

    const int tid = threadIdx.x;
    const int wid = tid >> 5;
    const int L   = tid & 31;

    const int m0  = blockIdx.y * 128;
    const int nt  = blockIdx.x;
    const int sel = nt >> 3;
    const int c0  = (nt & 7) * 128;
    const int n0  = nt * 128;

    const __nv_bfloat16* Ah = (isVid ? g_AVhi : g_AThi) + (size_t)m0 * D;
    const __nv_bfloat16* Al = (isVid ? g_AVlo : g_ATlo) + (size_t)m0 * D;
    const __nv_bfloat16* Bh = (isVid ? g_WVhi : g_WThi) + (size_t)sel * DD + (size_t)c0 * D;
    const __nv_bfloat16* Bl = (isVid ? g_WVlo : g_WTlo) + (size_t)sel * DD + (size_t)c0 * D;
    float* C = isVid ? g_projV : g_projT;

    // ---- cp.async copy mapping (per thread): 4 tiles x 4 x 16B ----------
    const int r     = tid >> 1;          // 0..127 tile row
    const int halfk = (tid & 1) * 32;    // bf16 col offset 0 / 32
    const uint32_t sw_store = (uint32_t)((r & 7) << 4);

    // ---- ldmatrix address components ------------------------------------
    const int rm = (wid >> 2) * 64;      // warp row base (0/64)
    const int cn = (wid & 3) * 32;       // warp col base (0/32/64/96)
    const int a_r  = L & 15;             // A: row within atom
    const int a_cb = (L >> 4) * 16;      // A: k-byte offset (0/16)
    const int b_r  = (L & 7) + ((L >> 4) << 3);  // B: n-row within 16-row pair
    const int b_cb = ((L >> 3) & 1) * 16;        // B: k-byte offset (0/16)
    const uint32_t a_sw = (uint32_t)((a_r & 7) << 4);
    const uint32_t b_sw = (uint32_t)((b_r & 7) << 4);

    float acc[4][4][4];
#pragma unroll
    for (int mi = 0; mi < 4; mi++)
#pragma unroll
        for (int ni = 0; ni < 4; ni++)
#pragma unroll
            for (int j = 0; j < 4; j++) acc[mi][ni][j] = 0.0f;

    // prefetch chunk 0
    {
        const __nv_bfloat16* srcs[4] = { Ah, Al, Bh, Bl };
#pragma unroll
        for (int tle = 0; tle < 4; ++tle) {
            const __nv_bfloat16* src = srcs[tle] + (size_t)r * D + halfk;
            uint32_t dstb = sa + tle * 16384;
#pragma unroll
            for (int i = 0; i < 4; ++i) {
                uint32_t bo = (uint32_t)(r * 128 + (halfk + i * 8) * 2) ^ sw_store;
                cp16(dstb + bo, src + i * 8);
            }
        }
        CP_COMMIT();
    }

    for (int c = 0; c < 16; ++c) {
        __syncthreads();   // prior compute on the stage we are about to fill is done
        if (c + 1 < 16) {
            const int k0 = (c + 1) * 64;
            const uint32_t sb = sa + ((c + 1) & 1) * 65536;
            const __nv_bfloat16* srcs[4] = { Ah, Al, Bh, Bl };
#pragma unroll
            for (int tle = 0; tle < 4; ++tle) {
                const __nv_bfloat16* src = srcs[tle] + (size_t)r * D + k0 + halfk;
                uint32_t dstb = sb + tle * 16384;
#pragma unroll
                for (int i = 0; i < 4; ++i) {
                    uint32_t bo = (uint32_t)(r * 128 + (halfk + i * 8) * 2) ^ sw_store;
                    cp16(dstb + bo, src + i * 8);
                }
            }
            CP_COMMIT();
            CP_WAIT(1);
        } else {
            CP_WAIT(0);
        }
        __syncthreads();   // chunk c data visible to all warps

        const uint32_t sb = sa + (c & 1) * 65536;
#pragma unroll
        for (int k16 = 0; k16 < 4; ++k16) {
            const int kb = k16 * 32;
            uint32_t ah[4][4], al[4][4], bhf[2][4], blf[2][4];
#pragma unroll
            for (int mi = 0; mi < 4; ++mi) {
                const int row = rm + mi * 16 + a_r;
                const uint32_t off = (uint32_t)(row * 128) +
                                     (((uint32_t)(kb + a_cb)) ^ a_sw);
                ldsm_x4(ah[mi], sb + off);
                ldsm_x4(al[mi], sb + 16384 + off);
            }
#pragma unroll
            for (int np = 0; np < 2; ++np) {
                const int row = cn + np * 16 + b_r;
                const uint32_t off = (uint32_t)(row * 128) +
                                     (((uint32_t)(kb + b_cb)) ^ b_sw);
                ldsm_x4(bhf[np], sb + 32768 + off);
                ldsm_x4(blf[np], sb + 49152 + off);
            }
#pragma unroll
            for (int mi = 0; mi < 4; ++mi) {
#pragma unroll
                for (int ni = 0; ni < 4; ++ni) {
                    const uint32_t* b2h = &bhf[ni >> 1][(ni & 1) * 2];
                    const uint32_t* b2l = &blf[ni >> 1][(ni & 1) * 2];
                    mma16816(acc[mi][ni], ah[mi], b2h);
                    mma16816(acc[mi][ni], ah[mi], b2l);
                    mma16816(acc[mi][ni], al[mi], b2h);
                }
            }
        }
    }

    // ---- epilogue: bias + store -----------------------------------------
    const int tq  = L >> 2;
    const int tc2 = (L & 3) * 2;
    const float* bp = bias.p[sel];
#pragma unroll
    for (int ni = 0; ni < 4; ++ni) {
        const int colg = n0 + cn + ni * 8 + tc2;
        const float b0 = __ldg(bp + c0 + cn + ni * 8 + tc2);
        const float b1 = __ldg(bp + c0 + cn + ni * 8 + tc2 + 1);
#pragma unroll
        for (int mi = 0; mi < 4; ++mi) {
            const int row = m0 + rm + mi * 16 + tq;
            float2 v0 = { acc[mi][ni][0] + b0, acc[mi][ni][1] + b1 };
            float2 v1 = { acc[mi][ni][2] + b0, acc[mi][ni][3] + b1 };
            *(float2*)(C + (size_t)row * PW + colg)       = v0;
            *(float2*)(C + (size_t)(row + 8) * PW + colg) = v1;
        }
    }
}

// ---------------------------------------------------------------------------
// Logits: S[b,h,q,k] = Q(b,q,h,:).K(b,k,h,:), masked fill -1e4.
// ---------------------------------------------------------------------------
__global__ __launch_bounds__(256) void logits_kernel(
    int isV, const void* vmask, const void* tmask)
{
    using namespace cfg;
    const int Lq = isV ? LV : LT;
    const int kslot = isV ? 2 : 3;
    float* S = isV ? g_Sv : g_St;
    const float* projQ = isV ? g_projV : g_projT;
    const void* qmask = isV ? vmask : tmask;

    const int bh = blockIdx.z;
    const int b  = bh >> 4;
    const int h  = bh & 15;
    const int q0 = blockIdx.y * 64;
    const int k0 = blockIdx.x * 64;
    const int t  = threadIdx.x;

    const bool segTxt = (k0 >= LV);
    const int qslot = segTxt ? 1 : 0;

    __shared__ float Qs[64][65];
    __shared__ float Ks[64][65];

    {
        const int r  = t >> 4;
        const int dc = (t & 15) * 4;
        const float* qp = projQ + ((size_t)(b * Lq + q0 + r)) * PW
                        + qslot * D + h * DH + dc;
        const float* kp;
        if (!segTxt)
            kp = g_projV + ((size_t)(b * LV + k0 + r)) * PW + kslot * D + h * DH + dc;
        else
            kp = g_projT + ((size_t)(b * LT + (k0 - LV) + r)) * PW + kslot * D + h * DH + dc;
#pragma unroll
        for (int it = 0; it < 4; it++) {
            const int row = r + it * 16;
            float4 qv = *(const float4*)(qp + (size_t)(it * 16) * PW);
            Qs[dc + 0][row] = qv.x; Qs[dc + 1][row] = qv.y;
            Qs[dc + 2][row] = qv.z; Qs[dc + 3][row] = qv.w;
            float4 kv = *(const float4*)(kp + (size_t)(it * 16) * PW);
            Ks[dc + 0][row] = kv.x; Ks[dc + 1][row] = kv.y;
            Ks[dc + 2][row] = kv.z; Ks[dc + 3][row] = kv.w;
        }
    }
    __syncthreads();

    const int ty = t >> 4;
    const int tx = t & 15;
    const int qb = ty * 4, kb = tx * 4;

    float acc[4][4] = {};
#pragma unroll 8
    for (int kk = 0; kk < 64; kk++) {
        float a[4], bb[4];
#pragma unroll
        for (int i = 0; i < 4; i++) a[i]  = Qs[kk][qb + i];
#pragma unroll
        for (int j = 0; j < 4; j++) bb[j] = Ks[kk][kb + j];
#pragma unroll
        for (int i = 0; i < 4; i++)
#pragma unroll
            for (int j = 0; j < 4; j++)
                acc[i][j] += a[i] * bb[j];
    }

#pragma unroll
    for (int i = 0; i < 4; i++) {
        const int q = q0 + qb + i;
        const bool mq = mask_at(qmask, b * Lq + q);
        float* srow = S + ((size_t)bh * Lq + q) * LK + k0 + kb;
#pragma unroll
        for (int j = 0; j < 4; j++) {
            const int k = k0 + kb + j;
            const bool mk = segTxt ? mask_at(tmask, b * LT + k - LV)
                                   : mask_at(vmask, b * LV + k);
            srow[j] = (mq && mk) ? acc[i][j] : -10000.0f;
        }
    }
}

// ---------------------------------------------------------------------------
__global__ __launch_bounds__(256) void softmax_kernel(int isV) {
    using namespace cfg;
    float* S = isV ? g_Sv : g_St;
    float* p = S + (size_t)blockIdx.x * LK;
    const int t = threadIdx.x;
    const int lane = t & 31, warp = t >> 5;

    float v[5];
    float mx = -1e30f;
#pragma unroll
    for (int i = 0; i < 5; i++) { v[i] = p[t + i * 256]; mx = fmaxf(mx, v[i]); }
#pragma unroll
    for (int o = 16; o; o >>= 1) mx = fmaxf(mx, __shfl_xor_sync(0xffffffffu, mx, o));

    __shared__ float red[8];
    if (lane == 0) red[warp] = mx;
    __syncthreads();
    float m_all = red[0];
#pragma unroll
    for (int i = 1; i < 8; i++) m_all = fmaxf(m_all, red[i]);

    float sum = 0.0f;
#pragma unroll
    for (int i = 0; i < 5; i++) { v[i] = __expf(v[i] - m_all); sum += v[i]; }
#pragma unroll
    for (int o = 16; o; o >>= 1) sum += __shfl_xor_sync(0xffffffffu, sum, o);
    __syncthreads();
    if (lane == 0) red[warp] = sum;
    __syncthreads();
    float s_all = 0.0f;
#pragma unroll
    for (int i = 0; i < 8; i++) s_all += red[i];

    const float sc = 0.125f / s_all;
#pragma unroll
    for (int i = 0; i < 5; i++) p[t + i * 256] = v[i] * sc;
}

// ---------------------------------------------------------------------------
__global__ __launch_bounds__(256) void pv_kernel(int isV, float* out) {
    using namespace cfg;
    const int Lq = isV ? LV : LT;
    const int vslot = isV ? 4 : 5;
    const float* S = isV ? g_Sv : g_St;

    const int bh = blockIdx.z;
    const int b  = bh >> 4;
    const int h  = bh & 15;
    const int q0 = blockIdx.y * 64;
    const int t  = threadIdx.x;

    __shared__ float Ps[64][65];
    __shared__ float Vs[64][65];

    const int ty = t >> 4, tx = t & 15;
    const int qb = ty * 4, db = tx * 4;

    float acc[4][4] = {};

    const int r  = t >> 4;
    const int cc = (t & 15) * 4;

    for (int k0 = 0; k0 < LK; k0 += 64) {
        const bool segTxt = (k0 >= LV);
        __syncthreads();
#pragma unroll
        for (int it = 0; it < 4; it++) {
            const int row = r + it * 16;
            float4 pv = *(const float4*)(S + ((size_t)bh * Lq + q0 + row) * LK + k0 + cc);
            Ps[cc + 0][row] = pv.x; Ps[cc + 1][row] = pv.y;
            Ps[cc + 2][row] = pv.z; Ps[cc + 3][row] = pv.w;
            const int kidx = k0 + row;
            const float* vp;
            if (!segTxt)
                vp = g_projV + ((size_t)(b * LV + kidx)) * PW + vslot * D + h * DH + cc;
            else
                vp = g_projT + ((size_t)(b * LT + kidx - LV)) * PW + vslot * D + h * DH + cc;
            float4 vv = *(const float4*)vp;
            Vs[row][cc + 0] = vv.x; Vs[row][cc + 1] = vv.y;
            Vs[row][cc + 2] = vv.z; Vs[row][cc + 3] = vv.w;
        }
        __syncthreads();
#pragma unroll 8
        for (int kk = 0; kk < 64; kk++) {
            float a[4], bb[4];
#pragma unroll
            for (int i = 0; i < 4; i++) a[i]  = Ps[kk][qb + i];
#pragma unroll
            for (int j = 0; j < 4; j++) bb[j] = Vs[kk][db + j];
#pragma unroll
            for (int i = 0; i < 4; i++)
#pragma unroll
                for (int j = 0; j < 4; j++)
                    acc[i][j] += a[i] * bb[j];
        }
    }

#pragma unroll
    for (int i = 0; i < 4; i++) {
        const int q = q0 + qb + i;
        float* orow = out + ((size_t)(b * Lq + q)) * D + h * DH + db;
#pragma unroll
        for (int j = 0; j < 4; j++) orow[j] = acc[i][j];
    }
}

// ---------------------------------------------------------------------------
extern "C" void kernel_launch(void* const* d_in, const int* in_sizes, int n_in,
                              void* d_out, int out_size) {
    using namespace cfg;
    const float* vid_feat = (const float*)d_in[0];
    const void*  vid_mask = d_in[1];
    const float* txt_feat = (const float*)d_in[2];
    const void*  txt_mask = d_in[3];
    const float* W_v2v = (const float*)d_in[4];
    const float* b_v2v = (const float*)d_in[5];
    const float* W_t2v = (const float*)d_in[6];
    const float* b_t2v = (const float*)d_in[7];
    const float* W_v2t = (const float*)d_in[8];
    const float* b_v2t = (const float*)d_in[9];
    const float* W_t2t = (const float*)d_in[10];
    const float* b_t2t = (const float*)d_in[11];
    float* out = (float*)d_out;

    detect_mask_mode<<<1, 32>>>((const unsigned int*)vid_mask);

    // ---- fp32 -> bf16 hi/lo conversions -------------------------------
    {
        const int n4A = (B * LV * D) / 4;
        const int n4T = (B * LT * D) / 4;
        const int n4W = DD / 4;
        convert_one<<<(n4A + 255) / 256, 256>>>(vid_feat, 0, 0, n4A);
        convert_one<<<(n4T + 255) / 256, 256>>>(txt_feat, 1, 0, n4T);
        const float* wv[6] = { W_v2v,          W_t2v,          W_v2v + DD,
                               W_v2t + DD,     W_v2v + 2 * DD, W_v2t + 2 * DD };
        const float* wt[6] = { W_v2t,          W_t2t,          W_t2v + DD,
                               W_t2t + DD,     W_t2v + 2 * DD, W_t2t + 2 * DD };
        for (int s = 0; s < 6; s++) {
            convert_one<<<(n4W + 255) / 256, 256>>>(wv[s], 2, s, n4W);
            convert_one<<<(n4W + 255) / 256, 256>>>(wt[s], 3, s, n4W);
        }
    }

    // ---- tensor-core projection GEMMs ----------------------------------
    const int SMEM_SZ = 2 * 65536 + 1024;
    cudaFuncSetAttribute(proj_mma, cudaFuncAttributeMaxDynamicSharedMemorySize, SMEM_SZ);

    TCBias bv; bv.p[0] = b_v2v; bv.p[1] = b_t2v; bv.p[2] = b_v2v + D;
               bv.p[3] = b_v2t + D; bv.p[4] = b_v2v + 2 * D; bv.p[5] = b_v2t + 2 * D;
    TCBias bt; bt.p[0] = b_v2t; bt.p[1] = b_t2t; bt.p[2] = b_t2v + D;
               bt.p[3] = b_t2t + D; bt.p[4] = b_t2v + 2 * D; bt.p[5] = b_t2t + 2 * D;

    proj_mma<<<dim3(PW / 128, (B * LV) / 128), 256, SMEM_SZ>>>(1, bv);
    proj_mma<<<dim3(PW / 128, (B * LT) / 128), 256, SMEM_SZ>>>(0, bt);

    // ---- attention -------------------------------------------------------
    logits_kernel<<<dim3(LK / 64, LV / 64, B * H), 256>>>(1, vid_mask, txt_mask);
    logits_kernel<<<dim3(LK / 64, LT / 64, B * H), 256>>>(0, vid_mask, txt_mask);

    softmax_kernel<<<B * H * LV, 256>>>(1);
    softmax_kernel<<<B * H * LT, 256>>>(0);

    pv_kernel<<<dim3(1, LV / 64, B * H), 256>>>(1, out);
    pv_kernel<<<dim3(1, LT / 64, B * H), 256>>>(0, out + (size_t)B * LV * D);
}

// round 9
// speedup vs baseline: 2.8348x; 1.8636x over previous
#include <cuda_runtime.h>
#include <cuda_bf16.h>
#include <cstdint>

// ---------------------------------------------------------------------------
// SegFormerXAttention: B=4, Lv=1024, Lt=256, H=16, DH=64, D=1024
//
//   0) detect_mask_mode : on-device dtype of the bool masks
//   1) convert_all      : fp32 -> (bf16 hi, bf16 lo) split of A and W slabs
//   2) proj_mma x2      : HMMA bf16 3-term-split GEMM; epilogue writes Q/K/V
//                         as bf16 hi/lo in attention layout [b][h][tok][64]
//   3) attn_fused       : flash-attention (QK^T + mask + online softmax + PV)
//                         in one kernel, HMMA 3-term split, no S scratch.
// ---------------------------------------------------------------------------

namespace cfg {
constexpr int D  = 1024;
constexpr int H  = 16;
constexpr int DH = 64;
constexpr int B  = 4;
constexpr int LV = 1024;
constexpr int LT = 256;
constexpr int LK = LV + LT;   // 1280
constexpr int DD = D * D;
}

// ---- input splits ----------------------------------------------------------
__device__ __nv_bfloat16 g_AVhi[(size_t)cfg::B * cfg::LV * cfg::D];
__device__ __nv_bfloat16 g_AVlo[(size_t)cfg::B * cfg::LV * cfg::D];
__device__ __nv_bfloat16 g_AThi[(size_t)cfg::B * cfg::LT * cfg::D];
__device__ __nv_bfloat16 g_ATlo[(size_t)cfg::B * cfg::LT * cfg::D];
__device__ __nv_bfloat16 g_WVhi[(size_t)6 * cfg::DD];
__device__ __nv_bfloat16 g_WVlo[(size_t)6 * cfg::DD];
__device__ __nv_bfloat16 g_WThi[(size_t)6 * cfg::DD];
__device__ __nv_bfloat16 g_WTlo[(size_t)6 * cfg::DD];

// ---- projection outputs, attention layout, bf16 hi/lo ----------------------
// Q: [b][slot(0/1)][h][tok][64]; K/V: [b][h][key 0..1279][64]
__device__ __nv_bfloat16 g_Qv_hi[(size_t)cfg::B * 2 * cfg::H * cfg::LV * 64];
__device__ __nv_bfloat16 g_Qv_lo[(size_t)cfg::B * 2 * cfg::H * cfg::LV * 64];
__device__ __nv_bfloat16 g_Qt_hi[(size_t)cfg::B * 2 * cfg::H * cfg::LT * 64];
__device__ __nv_bfloat16 g_Qt_lo[(size_t)cfg::B * 2 * cfg::H * cfg::LT * 64];
__device__ __nv_bfloat16 g_Kv_hi[(size_t)cfg::B * cfg::H * cfg::LK * 64];
__device__ __nv_bfloat16 g_Kv_lo[(size_t)cfg::B * cfg::H * cfg::LK * 64];
__device__ __nv_bfloat16 g_Kt_hi[(size_t)cfg::B * cfg::H * cfg::LK * 64];
__device__ __nv_bfloat16 g_Kt_lo[(size_t)cfg::B * cfg::H * cfg::LK * 64];
__device__ __nv_bfloat16 g_Vv_hi[(size_t)cfg::B * cfg::H * cfg::LK * 64];
__device__ __nv_bfloat16 g_Vv_lo[(size_t)cfg::B * cfg::H * cfg::LK * 64];
__device__ __nv_bfloat16 g_Vt_hi[(size_t)cfg::B * cfg::H * cfg::LK * 64];
__device__ __nv_bfloat16 g_Vt_lo[(size_t)cfg::B * cfg::H * cfg::LK * 64];

// 0 = float32 (1.0f/0.0f), 1 = int32 (1/0), 2 = packed uint8 bool
__device__ int g_maskMode;

__global__ void detect_mask_mode(const unsigned int* m) {
    if (threadIdx.x != 0) return;
    bool isF = false, isB = false;
    for (int i = 0; i < 64; i++) {
        unsigned int w = m[i];
        if (w == 0x3F800000u) isF = true;
        if (w == 0x01010101u) isB = true;
    }
    g_maskMode = isF ? 0 : (isB ? 2 : 1);
}

__device__ __forceinline__ bool mask_at(const void* m, int i) {
    const int mode = g_maskMode;
    if (mode == 0) return ((const float*)m)[i] != 0.0f;
    if (mode == 1) return ((const int*)m)[i] != 0;
    return ((const unsigned char*)m)[i] != 0;
}

// ---------------------------------------------------------------------------
// helpers
// ---------------------------------------------------------------------------
__device__ __forceinline__ uint32_t smem_u32(const void* p) {
    uint32_t a;
    asm("{ .reg .u64 t; cvta.to.shared.u64 t, %1; cvt.u32.u64 %0, t; }" : "=r"(a) : "l"(p));
    return a;
}
__device__ __forceinline__ void mma16816(float* d, const uint32_t* a, const uint32_t* b) {
    asm volatile(
        "mma.sync.aligned.m16n8k16.row.col.f32.bf16.bf16.f32 "
        "{%0,%1,%2,%3}, {%4,%5,%6,%7}, {%8,%9}, {%0,%1,%2,%3};"
        : "+f"(d[0]), "+f"(d[1]), "+f"(d[2]), "+f"(d[3])
        : "r"(a[0]), "r"(a[1]), "r"(a[2]), "r"(a[3]), "r"(b[0]), "r"(b[1]));
}
__device__ __forceinline__ void ldsm_x4(uint32_t* r, uint32_t addr) {
    asm volatile("ldmatrix.sync.aligned.m8n8.x4.shared.b16 {%0,%1,%2,%3}, [%4];"
                 : "=r"(r[0]), "=r"(r[1]), "=r"(r[2]), "=r"(r[3]) : "r"(addr));
}
__device__ __forceinline__ void ldsm_x4_t(uint32_t* r, uint32_t addr) {
    asm volatile("ldmatrix.sync.aligned.m8n8.x4.trans.shared.b16 {%0,%1,%2,%3}, [%4];"
                 : "=r"(r[0]), "=r"(r[1]), "=r"(r[2]), "=r"(r[3]) : "r"(addr));
}
__device__ __forceinline__ void cp16(uint32_t dst, const void* src) {
    asm volatile("cp.async.cg.shared.global [%0], [%1], 16;" :: "r"(dst), "l"(src));
}
#define CP_COMMIT() asm volatile("cp.async.commit_group;" ::: "memory")
#define CP_WAIT(N)  asm volatile("cp.async.wait_group %0;" :: "n"(N) : "memory")

// fp32 pair -> packed bf16 hi pair + bf16 lo pair
__device__ __forceinline__ void split2(float x, float y, uint32_t& hi, uint32_t& lo) {
    __nv_bfloat16 hx = __float2bfloat16(x), hy = __float2bfloat16(y);
    __nv_bfloat16 lx = __float2bfloat16(x - __bfloat162float(hx));
    __nv_bfloat16 ly = __float2bfloat16(y - __bfloat162float(hy));
    __nv_bfloat162 h2(hx, hy), l2(lx, ly);
    hi = *reinterpret_cast<uint32_t*>(&h2);
    lo = *reinterpret_cast<uint32_t*>(&l2);
}

// ---------------------------------------------------------------------------
// fp32 -> bf16 hi/lo split, all 14 slabs in one launch.
// dst: 0=AV 1=AT 2=WV(+slot) 3=WT(+slot)
// ---------------------------------------------------------------------------
struct CvtArgs { const float* src[14]; int dst[14]; int slot[14]; int n4[14]; };

__global__ __launch_bounds__(256) void convert_all(CvtArgs a) {
    const int job = blockIdx.y;
    const int i = blockIdx.x * 256 + threadIdx.x;
    if (i >= a.n4[job]) return;
    const int slot = a.slot[job];
    __nv_bfloat16 *hi, *lo;
    switch (a.dst[job]) {
        case 0:  hi = g_AVhi;                          lo = g_AVlo;                          break;
        case 1:  hi = g_AThi;                          lo = g_ATlo;                          break;
        case 2:  hi = g_WVhi + (size_t)slot * cfg::DD; lo = g_WVlo + (size_t)slot * cfg::DD; break;
        default: hi = g_WThi + (size_t)slot * cfg::DD; lo = g_WTlo + (size_t)slot * cfg::DD; break;
    }
    float4 v = ((const float4*)a.src[job])[i];
    uint32_t h01, l01, h23, l23;
    split2(v.x, v.y, h01, l01);
    split2(v.z, v.w, h23, l23);
    uint32_t* hp = (uint32_t*)(hi + (size_t)i * 4);
    uint32_t* lp = (uint32_t*)(lo + (size_t)i * 4);
    hp[0] = h01; hp[1] = h23;
    lp[0] = l01; lp[1] = l23;
}

// ---------------------------------------------------------------------------
// HMMA projection GEMM (as R6), epilogue -> bf16 hi/lo attention buffers.
// slot layout: 0,1 = Q (key-segment vid/txt); 2 = K v-stream; 3 = K t-stream;
//              4 = V v-stream; 5 = V t-stream.
// ---------------------------------------------------------------------------
struct TCBias { const float* p[6]; };

__global__ __launch_bounds__(256) void proj_mma(int isVid, TCBias bias) {
    using namespace cfg;
    extern __shared__ char sm[];
    uint32_t sbase = smem_u32(sm);
    uint32_t padb  = (1024u - (sbase & 1023u)) & 1023u;
    const uint32_t sa = sbase + padb;

    const int tid = threadIdx.x;
    const int wid = tid >> 5;
    const int L   = tid & 31;

    const int m0  = blockIdx.y * 128;
    const int nt  = blockIdx.x;
    const int sel = nt >> 3;
    const int c0  = (nt & 7) * 128;

    const __nv_bfloat16* Ah = (isVid ? g_AVhi : g_AThi) + (size_t)m0 * D;
    const __nv_bfloat16* Al = (isVid ? g_AVlo : g_ATlo) + (size_t)m0 * D;
    const __nv_bfloat16* Bh = (isVid ? g_WVhi : g_WThi) + (size_t)sel * DD + (size_t)c0 * D;
    const __nv_bfloat16* Bl = (isVid ? g_WVlo : g_WTlo) + (size_t)sel * DD + (size_t)c0 * D;

    const int r     = tid >> 1;
    const int halfk = (tid & 1) * 32;
    const uint32_t sw_store = (uint32_t)((r & 7) << 4);

    const int rm = (wid >> 2) * 64;
    const int cn = (wid & 3) * 32;
    const int a_r  = L & 15;
    const int a_cb = (L >> 4) * 16;
    const int b_r  = (L & 7) + ((L >> 4) << 3);
    const int b_cb = ((L >> 3) & 1) * 16;
    const uint32_t a_sw = (uint32_t)((a_r & 7) << 4);
    const uint32_t b_sw = (uint32_t)((b_r & 7) << 4);

    float acc[4][4][4];
#pragma unroll
    for (int mi = 0; mi < 4; mi++)
#pragma unroll
        for (int ni = 0; ni < 4; ni++)
#pragma unroll
            for (int j = 0; j < 4; j++) acc[mi][ni][j] = 0.0f;

    {
        const __nv_bfloat16* srcs[4] = { Ah, Al, Bh, Bl };
#pragma unroll
        for (int tle = 0; tle < 4; ++tle) {
            const __nv_bfloat16* src = srcs[tle] + (size_t)r * D + halfk;
            uint32_t dstb = sa + tle * 16384;
#pragma unroll
            for (int i = 0; i < 4; ++i) {
                uint32_t bo = (uint32_t)(r * 128 + (halfk + i * 8) * 2) ^ sw_store;
                cp16(dstb + bo, src + i * 8);
            }
        }
        CP_COMMIT();
    }

    for (int c = 0; c < 16; ++c) {
        __syncthreads();
        if (c + 1 < 16) {
            const int k0 = (c + 1) * 64;
            const uint32_t sb = sa + ((c + 1) & 1) * 65536;
            const __nv_bfloat16* srcs[4] = { Ah, Al, Bh, Bl };
#pragma unroll
            for (int tle = 0; tle < 4; ++tle) {
                const __nv_bfloat16* src = srcs[tle] + (size_t)r * D + k0 + halfk;
                uint32_t dstb = sb + tle * 16384;
#pragma unroll
                for (int i = 0; i < 4; ++i) {
                    uint32_t bo = (uint32_t)(r * 128 + (halfk + i * 8) * 2) ^ sw_store;
                    cp16(dstb + bo, src + i * 8);
                }
            }
            CP_COMMIT();
            CP_WAIT(1);
        } else {
            CP_WAIT(0);
        }
        __syncthreads();

        const uint32_t sb = sa + (c & 1) * 65536;
#pragma unroll
        for (int k16 = 0; k16 < 4; ++k16) {
            const int kb = k16 * 32;
            uint32_t ah[4][4], al[4][4], bhf[2][4], blf[2][4];
#pragma unroll
            for (int mi = 0; mi < 4; ++mi) {
                const int row = rm + mi * 16 + a_r;
                const uint32_t off = (uint32_t)(row * 128) +
                                     (((uint32_t)(kb + a_cb)) ^ a_sw);
                ldsm_x4(ah[mi], sb + off);
                ldsm_x4(al[mi], sb + 16384 + off);
            }
#pragma unroll
            for (int np = 0; np < 2; ++np) {
                const int row = cn + np * 16 + b_r;
                const uint32_t off = (uint32_t)(row * 128) +
                                     (((uint32_t)(kb + b_cb)) ^ b_sw);
                ldsm_x4(bhf[np], sb + 32768 + off);
                ldsm_x4(blf[np], sb + 49152 + off);
            }
#pragma unroll
            for (int mi = 0; mi < 4; ++mi) {
#pragma unroll
                for (int ni = 0; ni < 4; ++ni) {
                    const uint32_t* b2h = &bhf[ni >> 1][(ni & 1) * 2];
                    const uint32_t* b2l = &blf[ni >> 1][(ni & 1) * 2];
                    mma16816(acc[mi][ni], ah[mi], b2h);
                    mma16816(acc[mi][ni], ah[mi], b2l);
                    mma16816(acc[mi][ni], al[mi], b2h);
                }
            }
        }
    }

    // ---- epilogue: bias + hi/lo split -> attention buffers ----------------
    const int tq  = L >> 2;
    const int tc2 = (L & 3) * 2;
    const float* bp = bias.p[sel];
    const int Lqd = isVid ? LV : LT;

    __nv_bfloat16 *dstHi, *dstLo;
    switch (sel) {
        case 0: case 1: dstHi = isVid ? g_Qv_hi : g_Qt_hi;
                        dstLo = isVid ? g_Qv_lo : g_Qt_lo; break;
        case 2: dstHi = g_Kv_hi; dstLo = g_Kv_lo; break;
        case 3: dstHi = g_Kt_hi; dstLo = g_Kt_lo; break;
        case 4: dstHi = g_Vv_hi; dstLo = g_Vv_lo; break;
        default: dstHi = g_Vt_hi; dstLo = g_Vt_lo; break;
    }

#pragma unroll
    for (int ni = 0; ni < 4; ++ni) {
        const int col_local = c0 + cn + ni * 8 + tc2;     // 0..1023 within slot
        const int hh = col_local >> 6;
        const int dh = col_local & 63;
        const float b0v = __ldg(bp + col_local);
        const float b1v = __ldg(bp + col_local + 1);
#pragma unroll
        for (int mi = 0; mi < 4; ++mi) {
            const int rbase = m0 + rm + mi * 16 + tq;
#pragma unroll
            for (int hf = 0; hf < 2; ++hf) {
                const int row = rbase + hf * 8;
                const int bb  = isVid ? (row >> 10) : (row >> 8);
                const int tok = isVid ? (row & 1023) : (row & 255);
                const float vx = acc[mi][ni][hf * 2]     + b0v;
                const float vy = acc[mi][ni][hf * 2 + 1] + b1v;
                uint32_t h2, l2;
                split2(vx, vy, h2, l2);
                size_t idx2;
                if (sel < 2)
                    idx2 = ((((size_t)bb * 2 + sel) * H + hh) * Lqd + tok) * 64 + dh;
                else {
                    const int key = isVid ? tok : (LV + tok);
                    idx2 = (((size_t)bb * H + hh) * LK + key) * 64 + dh;
                }
                *(uint32_t*)(dstHi + idx2) = h2;
                *(uint32_t*)(dstLo + idx2) = l2;
            }
        }
    }
}

// ---------------------------------------------------------------------------
// Fused flash attention. Grid: 640 CTAs (512 vid q-tiles + 128 txt q-tiles).
// Per CTA: 128 q rows x full 1280 keys in 10 k-tiles of 128.
// SMEM: Q (4 tiles, 64 KB) + 2 KV stages (128 KB) + mask flags.
// ---------------------------------------------------------------------------
namespace asm_off {
constexpr uint32_t KV0   = 65536;
constexpr uint32_t STAGE = 65536;
constexpr uint32_t FLAGS = 196608;
}

__global__ __launch_bounds__(256, 1) void attn_fused(
    const void* vmask, const void* tmask, float* out)
{
    using namespace cfg;
    extern __shared__ char sm[];
    uint32_t sbase = smem_u32(sm);
    uint32_t padb  = (1024u - (sbase & 1023u)) & 1023u;
    const uint32_t sa = sbase + padb;
    char* smp = sm + padb;

    const int tid = threadIdx.x;
    const int w = tid >> 5;
    const int L = tid & 31;

    int idx = blockIdx.x;
    int isV, bh, qt;
    if (idx < 512) { isV = 1; bh = idx >> 3; qt = idx & 7; }
    else { idx -= 512; isV = 0; bh = idx >> 1; qt = idx & 1; }
    const int b = bh >> 4, h = bh & 15;
    const int Lq = isV ? LV : LT;
    const int q0 = qt * 128;

    const __nv_bfloat16 *Qhi, *Qlo, *Khi, *Klo, *Vhi, *Vlo;
    float* obase;
    if (isV) { Qhi = g_Qv_hi; Qlo = g_Qv_lo; Khi = g_Kv_hi; Klo = g_Kv_lo;
               Vhi = g_Vv_hi; Vlo = g_Vv_lo; obase = out; }
    else     { Qhi = g_Qt_hi; Qlo = g_Qt_lo; Khi = g_Kt_hi; Klo = g_Kt_lo;
               Vhi = g_Vt_hi; Vlo = g_Vt_lo; obase = out + (size_t)B * LV * D; }

    float* qff = (float*)(smp + asm_off::FLAGS);
    float* kff = qff + 128;

    const int r     = tid >> 1;
    const int halfk = (tid & 1) * 32;
    const uint32_t swr = (uint32_t)((r & 7) << 4);

    // ---- Q tiles (both slots, hi/lo) + KV stage 0 -------------------------
    {
#pragma unroll
        for (int s = 0; s < 2; s++) {
            const size_t src = ((((size_t)b * 2 + s) * H + h) * Lq + q0 + r) * 64 + halfk;
            const uint32_t dstb = sa + s * 32768;
#pragma unroll
            for (int i = 0; i < 4; i++) {
                uint32_t bo = (uint32_t)(r * 128 + (halfk + i * 8) * 2) ^ swr;
                cp16(dstb + bo,         Qhi + src + i * 8);
                cp16(dstb + 16384 + bo, Qlo + src + i * 8);
            }
        }
        const size_t src = (((size_t)b * H + h) * LK + r) * 64 + halfk;
        const uint32_t kv0 = sa + asm_off::KV0;
#pragma unroll
        for (int i = 0; i < 4; i++) {
            uint32_t bo = (uint32_t)(r * 128 + (halfk + i * 8) * 2) ^ swr;
            cp16(kv0 + bo,         Khi + src + i * 8);
            cp16(kv0 + 16384 + bo, Klo + src + i * 8);
            cp16(kv0 + 32768 + bo, Vhi + src + i * 8);
            cp16(kv0 + 49152 + bo, Vlo + src + i * 8);
        }
        CP_COMMIT();
    }

    // ---- mask flags --------------------------------------------------------
    const void* qmask = isV ? vmask : tmask;
    for (int i = tid; i < 128; i += 256)
        qff[i] = mask_at(qmask, b * Lq + q0 + i) ? 1.0f : 0.0f;
    for (int i = tid; i < LK; i += 256) {
        bool mk = (i < LV) ? mask_at(vmask, b * LV + i)
                           : mask_at(tmask, b * LT + i - LV);
        kff[i] = mk ? 1.0f : 0.0f;
    }
    __syncthreads();

    const int lq  = L >> 2;
    const int lc2 = (L & 3) * 2;
    const int a_r  = L & 15;
    const int a_cb = (L >> 4) * 16;
    const int b_r  = (L & 7) + ((L >> 4) << 3);
    const int b_cb = ((L >> 3) & 1) * 16;

    const float qf0 = qff[w * 16 + lq];
    const float qf1 = qff[w * 16 + lq + 8];

    float oacc[8][4];
#pragma unroll
    for (int a = 0; a < 8; a++)
#pragma unroll
        for (int j = 0; j < 4; j++) oacc[a][j] = 0.0f;
    float m0 = -1e30f, m1 = -1e30f, l0 = 0.0f, l1 = 0.0f;

    for (int kt = 0; kt < 10; ++kt) {
        __syncthreads();  // everyone done reading the stage we may overwrite
        if (kt + 1 < 10) {
            const uint32_t sb = sa + asm_off::KV0 + ((kt + 1) & 1) * asm_off::STAGE;
            const size_t src = (((size_t)b * H + h) * LK + (kt + 1) * 128 + r) * 64 + halfk;
#pragma unroll
            for (int i = 0; i < 4; i++) {
                uint32_t bo = (uint32_t)(r * 128 + (halfk + i * 8) * 2) ^ swr;
                cp16(sb + bo,         Khi + src + i * 8);
                cp16(sb + 16384 + bo, Klo + src + i * 8);
                cp16(sb + 32768 + bo, Vhi + src + i * 8);
                cp16(sb + 49152 + bo, Vlo + src + i * 8);
            }
            CP_COMMIT();
            CP_WAIT(1);
        } else {
            CP_WAIT(0);
        }
        __syncthreads();

        const uint32_t sKV = sa + asm_off::KV0 + (kt & 1) * asm_off::STAGE;
        const uint32_t qb_ = sa + ((kt < 8) ? 0 : 32768);

        // ---- S = Q K^T (3-term split) ----
        float sacc[16][4];
#pragma unroll
        for (int a = 0; a < 16; a++)
#pragma unroll
            for (int j = 0; j < 4; j++) sacc[a][j] = 0.0f;

#pragma unroll
        for (int kc = 0; kc < 4; ++kc) {
            const int arow = w * 16 + a_r;
            const uint32_t aoff = (uint32_t)(arow * 128) +
                (((uint32_t)(kc * 32 + a_cb)) ^ ((uint32_t)((arow & 7) << 4)));
            uint32_t aqh[4], aql[4];
            ldsm_x4(aqh, qb_ + aoff);
            ldsm_x4(aql, qb_ + 16384 + aoff);
#pragma unroll
            for (int g = 0; g < 8; ++g) {
                const int krow = g * 16 + b_r;
                const uint32_t koff = (uint32_t)(krow * 128) +
                    (((uint32_t)(kc * 32 + b_cb)) ^ ((uint32_t)((krow & 7) << 4)));
                uint32_t kh[4], kl[4];
                ldsm_x4(kh, sKV + koff);
                ldsm_x4(kl, sKV + 16384 + koff);
                mma16816(sacc[2 * g],     aqh, kh);
                mma16816(sacc[2 * g],     aqh, kl);
                mma16816(sacc[2 * g],     aql, kh);
                mma16816(sacc[2 * g + 1], aqh, kh + 2);
                mma16816(sacc[2 * g + 1], aqh, kl + 2);
                mma16816(sacc[2 * g + 1], aql, kh + 2);
            }
        }

        // ---- mask fill + row max ----
        const int kb0 = kt * 128;
        float rmax0 = -1e30f, rmax1 = -1e30f;
#pragma unroll
        for (int na = 0; na < 16; ++na) {
            const float kf0 = kff[kb0 + na * 8 + lc2];
            const float kf1 = kff[kb0 + na * 8 + lc2 + 1];
            float f;
            f = qf0 * kf0; sacc[na][0] = fmaf(sacc[na][0], f, fmaf(1e4f, f, -1e4f));
            f = qf0 * kf1; sacc[na][1] = fmaf(sacc[na][1], f, fmaf(1e4f, f, -1e4f));
            f = qf1 * kf0; sacc[na][2] = fmaf(sacc[na][2], f, fmaf(1e4f, f, -1e4f));
            f = qf1 * kf1; sacc[na][3] = fmaf(sacc[na][3], f, fmaf(1e4f, f, -1e4f));
            rmax0 = fmaxf(rmax0, fmaxf(sacc[na][0], sacc[na][1]));
            rmax1 = fmaxf(rmax1, fmaxf(sacc[na][2], sacc[na][3]));
        }
        rmax0 = fmaxf(rmax0, __shfl_xor_sync(0xffffffffu, rmax0, 1));
        rmax0 = fmaxf(rmax0, __shfl_xor_sync(0xffffffffu, rmax0, 2));
        rmax1 = fmaxf(rmax1, __shfl_xor_sync(0xffffffffu, rmax1, 1));
        rmax1 = fmaxf(rmax1, __shfl_xor_sync(0xffffffffu, rmax1, 2));

        const float mn0 = fmaxf(m0, rmax0), mn1 = fmaxf(m1, rmax1);
        const float sc0 = __expf(m0 - mn0), sc1 = __expf(m1 - mn1);

        float sum0 = 0.0f, sum1 = 0.0f;
#pragma unroll
        for (int na = 0; na < 16; ++na) {
            sacc[na][0] = __expf(sacc[na][0] - mn0);
            sacc[na][1] = __expf(sacc[na][1] - mn0);
            sacc[na][2] = __expf(sacc[na][2] - mn1);
            sacc[na][3] = __expf(sacc[na][3] - mn1);
            sum0 += sacc[na][0] + sacc[na][1];
            sum1 += sacc[na][2] + sacc[na][3];
        }
        sum0 += __shfl_xor_sync(0xffffffffu, sum0, 1);
        sum0 += __shfl_xor_sync(0xffffffffu, sum0, 2);
        sum1 += __shfl_xor_sync(0xffffffffu, sum1, 1);
        sum1 += __shfl_xor_sync(0xffffffffu, sum1, 2);
        l0 = l0 * sc0 + sum0; m0 = mn0;
        l1 = l1 * sc1 + sum1; m1 = mn1;

#pragma unroll
        for (int a = 0; a < 8; a++) {
            oacc[a][0] *= sc0; oacc[a][1] *= sc0;
            oacc[a][2] *= sc1; oacc[a][3] *= sc1;
        }

        // ---- O += P V (3-term split) ----
        const uint32_t sV = sKV + 32768;
#pragma unroll
        for (int kc2 = 0; kc2 < 8; ++kc2) {
            uint32_t ah[4], al[4];
            split2(sacc[2 * kc2][0],     sacc[2 * kc2][1],     ah[0], al[0]);
            split2(sacc[2 * kc2][2],     sacc[2 * kc2][3],     ah[1], al[1]);
            split2(sacc[2 * kc2 + 1][0], sacc[2 * kc2 + 1][1], ah[2], al[2]);
            split2(sacc[2 * kc2 + 1][2], sacc[2 * kc2 + 1][3], ah[3], al[3]);
            const int vrow = kc2 * 16 + (L & 15);
            const uint32_t vsw = (uint32_t)((vrow & 7) << 4);
#pragma unroll
            for (int ng = 0; ng < 4; ++ng) {
                const uint32_t vcolb = (uint32_t)((ng * 16 + ((L >> 4) << 3)) * 2);
                const uint32_t voff = (uint32_t)(vrow * 128) + (vcolb ^ vsw);
                uint32_t bvh[4], bvl[4];
                ldsm_x4_t(bvh, sV + voff);
                ldsm_x4_t(bvl, sV + 16384 + voff);
                mma16816(oacc[2 * ng],     ah, bvh);
                mma16816(oacc[2 * ng],     ah, bvl);
                mma16816(oacc[2 * ng],     al, bvh);
                mma16816(oacc[2 * ng + 1], ah, bvh + 2);
                mma16816(oacc[2 * ng + 1], ah, bvl + 2);
                mma16816(oacc[2 * ng + 1], al, bvh + 2);
            }
        }
    }

    // ---- write: out[b][q][h][dh] = O * (0.125 / l) -------------------------
    const float scale0 = 0.125f / l0;
    const float scale1 = 0.125f / l1;
    const int qrow0 = q0 + w * 16 + lq;
    float* op0 = obase + ((size_t)(b * Lq + qrow0)) * D + h * 64;
    float* op1 = op0 + (size_t)8 * D;
#pragma unroll
    for (int na = 0; na < 8; ++na) {
        float2 v0 = { oacc[na][0] * scale0, oacc[na][1] * scale0 };
        float2 v1 = { oacc[na][2] * scale1, oacc[na][3] * scale1 };
        *(float2*)(op0 + na * 8 + lc2) = v0;
        *(float2*)(op1 + na * 8 + lc2) = v1;
    }
}

// ---------------------------------------------------------------------------
extern "C" void kernel_launch(void* const* d_in, const int* in_sizes, int n_in,
                              void* d_out, int out_size) {
    using namespace cfg;
    const float* vid_feat = (const float*)d_in[0];
    const void*  vid_mask = d_in[1];
    const float* txt_feat = (const float*)d_in[2];
    const void*  txt_mask = d_in[3];
    const float* W_v2v = (const float*)d_in[4];
    const float* b_v2v = (const float*)d_in[5];
    const float* W_t2v = (const float*)d_in[6];
    const float* b_t2v = (const float*)d_in[7];
    const float* W_v2t = (const float*)d_in[8];
    const float* b_v2t = (const float*)d_in[9];
    const float* W_t2t = (const float*)d_in[10];
    const float* b_t2t = (const float*)d_in[11];
    float* out = (float*)d_out;

    detect_mask_mode<<<1, 32>>>((const unsigned int*)vid_mask);

    // ---- conversions (single launch) ------------------------------------
    {
        CvtArgs a;
        const float* wv[6] = { W_v2v,          W_t2v,          W_v2v + DD,
                               W_v2t + DD,     W_v2v + 2 * DD, W_v2t + 2 * DD };
        const float* wt[6] = { W_v2t,          W_t2t,          W_t2v + DD,
                               W_t2t + DD,     W_t2v + 2 * DD, W_t2t + 2 * DD };
        a.src[0] = vid_feat; a.dst[0] = 0; a.slot[0] = 0; a.n4[0] = (B * LV * D) / 4;
        a.src[1] = txt_feat; a.dst[1] = 1; a.slot[1] = 0; a.n4[1] = (B * LT * D) / 4;
        for (int s = 0; s < 6; s++) {
            a.src[2 + s] = wv[s]; a.dst[2 + s] = 2; a.slot[2 + s] = s; a.n4[2 + s] = DD / 4;
            a.src[8 + s] = wt[s]; a.dst[8 + s] = 3; a.slot[8 + s] = s; a.n4[8 + s] = DD / 4;
        }
        convert_all<<<dim3(4096, 14), 256>>>(a);
    }

    // ---- projection GEMMs ------------------------------------------------
    const int PROJ_SMEM = 2 * 65536 + 1024;
    cudaFuncSetAttribute(proj_mma, cudaFuncAttributeMaxDynamicSharedMemorySize, PROJ_SMEM);

    TCBias bv; bv.p[0] = b_v2v; bv.p[1] = b_t2v; bv.p[2] = b_v2v + D;
               bv.p[3] = b_v2t + D; bv.p[4] = b_v2v + 2 * D; bv.p[5] = b_v2t + 2 * D;
    TCBias bt; bt.p[0] = b_v2t; bt.p[1] = b_t2t; bt.p[2] = b_t2v + D;
               bt.p[3] = b_t2t + D; bt.p[4] = b_t2v + 2 * D; bt.p[5] = b_t2t + 2 * D;

    proj_mma<<<dim3(48, (B * LV) / 128), 256, PROJ_SMEM>>>(1, bv);
    proj_mma<<<dim3(48, (B * LT) / 128), 256, PROJ_SMEM>>>(0, bt);

    // ---- fused attention --------------------------------------------------
    const int ATT_SMEM = 196608 + 512 + 5120 + 1024;   // 203264
    cudaFuncSetAttribute(attn_fused, cudaFuncAttributeMaxDynamicSharedMemorySize, ATT_SMEM);
    attn_fused<<<640, 256, ATT_SMEM>>>(vid_mask, txt_mask, out);
}